// round 1
// baseline (speedup 1.0000x reference)
#include <cuda_runtime.h>
#include <cuda_bf16.h>

// Chamfer distance matrix, B=32, G=64, N=32, C=3.
// out[b,g1,g2] = mean_n min_m d[n,m] + mean_m min_n d[n,m]
// with d = |x1-x2|^2 expanded as n1 + n2 - 2*dot.
//
// Block = one (b,g1). Stages all x2 groups of batch b in smem as float4
// (x,y,z,norm) for single-LDS.128 broadcast loads. 8 warps, each warp
// handles 8 g2 groups. Both min directions computed lane-locally
// (matrix evaluated twice) to avoid per-column cross-lane reductions;
// a single butterfly sum per (g1,g2) pair produces the means.

#define G_GROUPS 64
#define N_PTS    32

__global__ __launch_bounds__(256, 1)
void chamfer_matrix_kernel(const float* __restrict__ x1,
                           const float* __restrict__ x2,
                           float* __restrict__ out)
{
    __shared__ float4 s2[G_GROUPS * N_PTS];  // 32 KB: x2 batch slice, packed
    __shared__ float4 s1[N_PTS];             // x1 group, packed

    const int bg  = blockIdx.x;        // b*64 + g1
    const int b   = bg >> 6;
    const int tid = threadIdx.x;

    // Stage x2[b] : 2048 points, 8 per thread. Coalesced 3-float reads.
    const float* __restrict__ x2b = x2 + (size_t)b * G_GROUPS * N_PTS * 3;
    #pragma unroll
    for (int i = tid; i < G_GROUPS * N_PTS; i += 256) {
        const float X = x2b[i * 3 + 0];
        const float Y = x2b[i * 3 + 1];
        const float Z = x2b[i * 3 + 2];
        s2[i] = make_float4(X, Y, Z, fmaf(X, X, fmaf(Y, Y, Z * Z)));
    }
    // Stage x1[b,g1] : 32 points.
    const float* __restrict__ x1g = x1 + (size_t)bg * N_PTS * 3;
    if (tid < N_PTS) {
        const float X = x1g[tid * 3 + 0];
        const float Y = x1g[tid * 3 + 1];
        const float Z = x1g[tid * 3 + 2];
        s1[tid] = make_float4(X, Y, Z, fmaf(X, X, fmaf(Y, Y, Z * Z)));
    }
    __syncthreads();

    const int wid  = tid >> 5;
    const int lane = tid & 31;

    const float4 p1 = s1[lane];   // lane n's x1 point (dir-1 owner)

    #pragma unroll
    for (int gi = 0; gi < 8; gi++) {
        const int g2 = wid * 8 + gi;
        const float4* __restrict__ q2 = &s2[g2 * N_PTS];

        const float4 p2 = q2[lane];  // lane m's x2 point (dir-2 owner)

        float min1 = 3.402823466e+38f;
        float min2 = 3.402823466e+38f;

        #pragma unroll
        for (int m = 0; m < N_PTS; m++) {
            // dir 1: d'[n][m] = n2[m] - 2 * <p1[n], q[m]>   (n1 folded after min)
            const float4 q = q2[m];                       // broadcast LDS.128
            const float dot1 = fmaf(p1.x, q.x, fmaf(p1.y, q.y, p1.z * q.z));
            min1 = fminf(min1, fmaf(-2.0f, dot1, q.w));

            // dir 2: d'[n][m] = n1[n] - 2 * <p2[m], r[n]>   (n2 folded after min)
            const float4 r = s1[m];                       // broadcast LDS.128
            const float dot2 = fmaf(p2.x, r.x, fmaf(p2.y, r.y, p2.z * r.z));
            min2 = fminf(min2, fmaf(-2.0f, dot2, r.w));
        }

        // sum_n dist1[n] + sum_m dist2[m]  via one butterfly reduction
        float v = (min1 + p1.w) + (min2 + p2.w);
        #pragma unroll
        for (int o = 16; o; o >>= 1)
            v += __shfl_xor_sync(0xffffffffu, v, o);

        if (lane == 0)
            out[bg * G_GROUPS + g2] = v * (1.0f / 32.0f);
    }
}

extern "C" void kernel_launch(void* const* d_in, const int* in_sizes, int n_in,
                              void* d_out, int out_size) {
    const float* x1  = (const float*)d_in[0];  // xyz1_matrix [32,64,32,3]
    const float* x2  = (const float*)d_in[1];  // xyz2_matrix [32,64,32,3]
    float*       out = (float*)d_out;          // [32,64,64]
    chamfer_matrix_kernel<<<32 * 64, 256>>>(x1, x2, out);
}

// round 2
// speedup vs baseline: 1.2125x; 1.2125x over previous
#include <cuda_runtime.h>
#include <cuda_bf16.h>

// Chamfer distance matrix, B=32, G=64, N=32, C=3.
// R2: packed f32x2 FMA (Blackwell FFMA2) over g2-group *pairs*, with the x2
// batch slice staged in smem pre-packed pairwise so each LDS.128 delivers two
// already-packed b64 operands. Both min directions stay lane-local; running
// mins kept as scalars (no min.f32x2 in PTX). __launch_bounds__(256,2) for
// 2 CTAs/SM.

#define NP 32

typedef unsigned long long u64;

static __device__ __forceinline__ u64 pack2(float lo, float hi) {
    u64 r; asm("mov.b64 %0, {%1, %2};" : "=l"(r) : "f"(lo), "f"(hi)); return r;
}
static __device__ __forceinline__ float2 unpack2(u64 v) {
    float2 f; asm("mov.b64 {%0, %1}, %2;" : "=f"(f.x), "=f"(f.y) : "l"(v)); return f;
}
static __device__ __forceinline__ u64 fma2(u64 a, u64 b, u64 c) {
    u64 d; asm("fma.rn.f32x2 %0, %1, %2, %3;" : "=l"(d) : "l"(a), "l"(b), "l"(c)); return d;
}
static __device__ __forceinline__ u64 mul2(u64 a, u64 b) {
    u64 d; asm("mul.rn.f32x2 %0, %1, %2;" : "=l"(d) : "l"(a), "l"(b)); return d;
}

__global__ __launch_bounds__(256, 2)
void chamfer_matrix_kernel(const float* __restrict__ x1,
                           const float* __restrict__ x2,
                           float* __restrict__ out)
{
    // Pair-packed x2 slice. For pair p (= groups 2p, 2p+1), point m:
    //   s2a[p*32+m] = {a.x, b.x, a.y, b.y}  -> as ulonglong2: .x={ax,bx} .y={ay,by}
    //   s2b[p*32+m] = {a.z, b.z, a.w, b.w}  -> .x={az,bz} .y={aw,bw}
    __shared__ ulonglong2 s2a[32 * NP];   // 16 KB
    __shared__ ulonglong2 s2b[32 * NP];   // 16 KB
    __shared__ float4 s1[NP];

    const int bg  = blockIdx.x;   // b*64 + g1
    const int b   = bg >> 6;
    const int tid = threadIdx.x;

    // Stage x2[b]: 2048 points, pre-packed pairwise.
    const float* __restrict__ x2b = x2 + (size_t)b * 64 * NP * 3;
    #pragma unroll
    for (int i = tid; i < 64 * NP; i += 256) {
        const float X = x2b[i * 3 + 0];
        const float Y = x2b[i * 3 + 1];
        const float Z = x2b[i * 3 + 2];
        const float W = fmaf(X, X, fmaf(Y, Y, Z * Z));
        const int g = i >> 5, m = i & 31;
        const int p = g >> 1, h = g & 1;
        float* da = (float*)&s2a[p * NP + m];
        float* db = (float*)&s2b[p * NP + m];
        da[0 + h] = X;  da[2 + h] = Y;
        db[0 + h] = Z;  db[2 + h] = W;
    }
    // Stage x1[b,g1].
    const float* __restrict__ x1g = x1 + (size_t)bg * NP * 3;
    if (tid < NP) {
        const float X = x1g[tid * 3 + 0];
        const float Y = x1g[tid * 3 + 1];
        const float Z = x1g[tid * 3 + 2];
        s1[tid] = make_float4(X, Y, Z, fmaf(X, X, fmaf(Y, Y, Z * Z)));
    }
    __syncthreads();

    const int wid  = tid >> 5;
    const int lane = tid & 31;

    const float4 p1 = s1[lane];
    const u64 px1  = pack2(p1.x, p1.x);
    const u64 py1  = pack2(p1.y, p1.y);
    const u64 pz1  = pack2(p1.z, p1.z);
    const u64 neg2 = pack2(-2.0f, -2.0f);

    // Each warp owns 4 g2-pairs: pair index wid*4+j -> groups (2*(wid*4+j), +1).
    u64 p2x[4], p2y[4], p2z[4], p2w[4];
    #pragma unroll
    for (int j = 0; j < 4; j++) {
        const ulonglong2 va = s2a[(wid * 4 + j) * NP + lane];
        const ulonglong2 vb = s2b[(wid * 4 + j) * NP + lane];
        p2x[j] = va.x;  p2y[j] = va.y;
        p2z[j] = vb.x;  p2w[j] = vb.y;
    }

    float min1a[4], min1b[4], min2a[4], min2b[4];
    #pragma unroll
    for (int j = 0; j < 4; j++) {
        min1a[j] = min1b[j] = min2a[j] = min2b[j] = 3.402823466e+38f;
    }

    #pragma unroll 4
    for (int m = 0; m < NP; m++) {
        const float4 r = s1[m];                       // broadcast LDS.128
        const u64 rx = pack2(r.x, r.x);
        const u64 ry = pack2(r.y, r.y);
        const u64 rz = pack2(r.z, r.z);
        const u64 rw = pack2(r.w, r.w);
        #pragma unroll
        for (int j = 0; j < 4; j++) {
            // dir 1 (lane = n): d' = q.w - 2*dot(p1, q) for both groups at once
            const ulonglong2 va = s2a[(wid * 4 + j) * NP + m];   // broadcast LDS.128
            const ulonglong2 vb = s2b[(wid * 4 + j) * NP + m];   // broadcast LDS.128
            const u64 dot1 = fma2(px1, va.x, fma2(py1, va.y, mul2(pz1, vb.x)));
            const float2 d1 = unpack2(fma2(dot1, neg2, vb.y));
            min1a[j] = fminf(min1a[j], d1.x);
            min1b[j] = fminf(min1b[j], d1.y);
            // dir 2 (lane = m): d' = r.w - 2*dot(p2, r) for both groups at once
            const u64 dot2 = fma2(p2x[j], rx, fma2(p2y[j], ry, mul2(p2z[j], rz)));
            const float2 d2 = unpack2(fma2(dot2, neg2, rw));
            min2a[j] = fminf(min2a[j], d2.x);
            min2b[j] = fminf(min2b[j], d2.y);
        }
    }

    // Finalize: fold lane-constant norms, butterfly-sum, store two g2 per j.
    #pragma unroll
    for (int j = 0; j < 4; j++) {
        const float2 w2 = unpack2(p2w[j]);
        float va = (min1a[j] + p1.w) + (min2a[j] + w2.x);
        float vb = (min1b[j] + p1.w) + (min2b[j] + w2.y);
        #pragma unroll
        for (int o = 16; o; o >>= 1) {
            va += __shfl_xor_sync(0xffffffffu, va, o);
            vb += __shfl_xor_sync(0xffffffffu, vb, o);
        }
        if (lane == 0) {
            const int g2 = (wid * 4 + j) * 2;
            out[bg * 64 + g2]     = va * (1.0f / 32.0f);
            out[bg * 64 + g2 + 1] = vb * (1.0f / 32.0f);
        }
    }
}

extern "C" void kernel_launch(void* const* d_in, const int* in_sizes, int n_in,
                              void* d_out, int out_size) {
    const float* x1  = (const float*)d_in[0];  // xyz1_matrix [32,64,32,3]
    const float* x2  = (const float*)d_in[1];  // xyz2_matrix [32,64,32,3]
    float*       out = (float*)d_out;          // [32,64,64]
    chamfer_matrix_kernel<<<32 * 64, 256>>>(x1, x2, out);
}

// round 3
// speedup vs baseline: 1.4724x; 1.2144x over previous
#include <cuda_runtime.h>
#include <cuda_bf16.h>

// Chamfer distance matrix, B=32, G=64, N=32, C=3.
// R3: each block handles a (b, g1-PAIR); the expensive per-m s2 broadcast
// loads (8 LDS.128) are reused across both g1 groups, cutting smem traffic
// per work-unit ~44% (L1 was the 74% binding pipe). Lane-owned operands are
// pre-scaled by -2 so each 3D dot+scale+bias is 3 FFMA2 instead of 4 packed
// ops. Packed f32x2 over g2-group pairs as in R2.

#define NP 32

typedef unsigned long long u64;

static __device__ __forceinline__ u64 pack2(float lo, float hi) {
    u64 r; asm("mov.b64 %0, {%1, %2};" : "=l"(r) : "f"(lo), "f"(hi)); return r;
}
static __device__ __forceinline__ float2 unpack2(u64 v) {
    float2 f; asm("mov.b64 {%0, %1}, %2;" : "=f"(f.x), "=f"(f.y) : "l"(v)); return f;
}
static __device__ __forceinline__ u64 fma2(u64 a, u64 b, u64 c) {
    u64 d; asm("fma.rn.f32x2 %0, %1, %2, %3;" : "=l"(d) : "l"(a), "l"(b), "l"(c)); return d;
}
static __device__ __forceinline__ u64 mul2(u64 a, u64 b) {
    u64 d; asm("mul.rn.f32x2 %0, %1, %2;" : "=l"(d) : "l"(a), "l"(b)); return d;
}

__global__ __launch_bounds__(256, 2)
void chamfer_matrix_kernel(const float* __restrict__ x1,
                           const float* __restrict__ x2,
                           float* __restrict__ out)
{
    // Pair-packed x2 slice: for g2-pair p, point m:
    //   s2a[p*32+m] = {a.x,b.x, a.y,b.y}   (ulonglong2 .x .y)
    //   s2b[p*32+m] = {a.z,b.z, a.w,b.w}
    __shared__ ulonglong2 s2a[32 * NP];   // 16 KB
    __shared__ ulonglong2 s2b[32 * NP];   // 16 KB
    __shared__ float4 s1A[NP];
    __shared__ float4 s1B[NP];

    const int blk = blockIdx.x;        // b*32 + g1pair
    const int b   = blk >> 5;
    const int gp  = blk & 31;          // g1 pair -> groups 2gp, 2gp+1
    const int tid = threadIdx.x;

    // Stage x2[b]: 2048 points, pre-packed pairwise.
    const float* __restrict__ x2b = x2 + (size_t)b * 64 * NP * 3;
    #pragma unroll
    for (int i = tid; i < 64 * NP; i += 256) {
        const float X = x2b[i * 3 + 0];
        const float Y = x2b[i * 3 + 1];
        const float Z = x2b[i * 3 + 2];
        const float W = fmaf(X, X, fmaf(Y, Y, Z * Z));
        const int g = i >> 5, m = i & 31;
        const int p = g >> 1, h = g & 1;
        float* da = (float*)&s2a[p * NP + m];
        float* db = (float*)&s2b[p * NP + m];
        da[0 + h] = X;  da[2 + h] = Y;
        db[0 + h] = Z;  db[2 + h] = W;
    }
    // Stage the two x1 groups.
    if (tid < 2 * NP) {
        const int h = tid >> 5, m = tid & 31;
        const float* __restrict__ p = x1 + (size_t)((b * 64 + 2 * gp + h) * NP + m) * 3;
        const float X = p[0], Y = p[1], Z = p[2];
        const float4 v = make_float4(X, Y, Z, fmaf(X, X, fmaf(Y, Y, Z * Z)));
        if (h == 0) s1A[m] = v; else s1B[m] = v;
    }
    __syncthreads();

    const int wid  = tid >> 5;
    const int lane = tid & 31;

    const float4 p1A = s1A[lane];
    const float4 p1B = s1B[lane];
    // Pre-scaled (-2x) splats for dir-1 dots.
    const u64 pxA = pack2(-2.0f * p1A.x, -2.0f * p1A.x);
    const u64 pyA = pack2(-2.0f * p1A.y, -2.0f * p1A.y);
    const u64 pzA = pack2(-2.0f * p1A.z, -2.0f * p1A.z);
    const u64 pxB = pack2(-2.0f * p1B.x, -2.0f * p1B.x);
    const u64 pyB = pack2(-2.0f * p1B.y, -2.0f * p1B.y);
    const u64 pzB = pack2(-2.0f * p1B.z, -2.0f * p1B.z);

    // Each warp owns 4 g2-pairs; lane holds its x2 point pair, pre-scaled by -2.
    const u64 neg2 = pack2(-2.0f, -2.0f);
    u64 p2x[4], p2y[4], p2z[4], p2w[4];
    #pragma unroll
    for (int j = 0; j < 4; j++) {
        const ulonglong2 va = s2a[(wid * 4 + j) * NP + lane];
        const ulonglong2 vb = s2b[(wid * 4 + j) * NP + lane];
        p2x[j] = mul2(va.x, neg2);
        p2y[j] = mul2(va.y, neg2);
        p2z[j] = mul2(vb.x, neg2);
        p2w[j] = vb.y;                 // unscaled norms (folded after min)
    }

    const float FLTMAX = 3.402823466e+38f;
    float m1aA[4], m1bA[4], m1aB[4], m1bB[4];   // dir-1 mins (lane = n)
    float m2aA[4], m2bA[4], m2aB[4], m2bB[4];   // dir-2 mins (lane = m)
    #pragma unroll
    for (int j = 0; j < 4; j++) {
        m1aA[j] = m1bA[j] = m1aB[j] = m1bB[j] = FLTMAX;
        m2aA[j] = m2bA[j] = m2aB[j] = m2bB[j] = FLTMAX;
    }

    #pragma unroll 4
    for (int m = 0; m < NP; m++) {
        const float4 rA = s1A[m];                 // broadcast LDS.128
        const float4 rB = s1B[m];                 // broadcast LDS.128
        const u64 rxA = pack2(rA.x, rA.x), ryA = pack2(rA.y, rA.y);
        const u64 rzA = pack2(rA.z, rA.z), rwA = pack2(rA.w, rA.w);
        const u64 rxB = pack2(rB.x, rB.x), ryB = pack2(rB.y, rB.y);
        const u64 rzB = pack2(rB.z, rB.z), rwB = pack2(rB.w, rB.w);
        #pragma unroll
        for (int j = 0; j < 4; j++) {
            const ulonglong2 va = s2a[(wid * 4 + j) * NP + m];   // broadcast LDS.128
            const ulonglong2 vb = s2b[(wid * 4 + j) * NP + m];   // broadcast LDS.128
            // dir 1 (lane = n): d' = q.w - 2<p1, q>, both g2 groups at once.
            const float2 d1A = unpack2(fma2(pxA, va.x, fma2(pyA, va.y, fma2(pzA, vb.x, vb.y))));
            m1aA[j] = fminf(m1aA[j], d1A.x);  m1bA[j] = fminf(m1bA[j], d1A.y);
            const float2 d1B = unpack2(fma2(pxB, va.x, fma2(pyB, va.y, fma2(pzB, vb.x, vb.y))));
            m1aB[j] = fminf(m1aB[j], d1B.x);  m1bB[j] = fminf(m1bB[j], d1B.y);
            // dir 2 (lane = m): d' = r.w - 2<p2, r>, both g2 groups at once.
            const float2 d2A = unpack2(fma2(p2x[j], rxA, fma2(p2y[j], ryA, fma2(p2z[j], rzA, rwA))));
            m2aA[j] = fminf(m2aA[j], d2A.x);  m2bA[j] = fminf(m2bA[j], d2A.y);
            const float2 d2B = unpack2(fma2(p2x[j], rxB, fma2(p2y[j], ryB, fma2(p2z[j], rzB, rwB))));
            m2aB[j] = fminf(m2aB[j], d2B.x);  m2bB[j] = fminf(m2bB[j], d2B.y);
        }
    }

    // Finalize: fold lane-constant norms, butterfly-sum, store.
    const int g1A = b * 64 + 2 * gp;
    #pragma unroll
    for (int j = 0; j < 4; j++) {
        const float2 w2 = unpack2(p2w[j]);
        float vaA = (m1aA[j] + p1A.w) + (m2aA[j] + w2.x);
        float vbA = (m1bA[j] + p1A.w) + (m2bA[j] + w2.y);
        float vaB = (m1aB[j] + p1B.w) + (m2aB[j] + w2.x);
        float vbB = (m1bB[j] + p1B.w) + (m2bB[j] + w2.y);
        #pragma unroll
        for (int o = 16; o; o >>= 1) {
            vaA += __shfl_xor_sync(0xffffffffu, vaA, o);
            vbA += __shfl_xor_sync(0xffffffffu, vbA, o);
            vaB += __shfl_xor_sync(0xffffffffu, vaB, o);
            vbB += __shfl_xor_sync(0xffffffffu, vbB, o);
        }
        if (lane == 0) {
            const int g2 = (wid * 4 + j) * 2;
            out[(size_t)g1A * 64 + g2]            = vaA * (1.0f / 32.0f);
            out[(size_t)g1A * 64 + g2 + 1]        = vbA * (1.0f / 32.0f);
            out[(size_t)(g1A + 1) * 64 + g2]      = vaB * (1.0f / 32.0f);
            out[(size_t)(g1A + 1) * 64 + g2 + 1]  = vbB * (1.0f / 32.0f);
        }
    }
}

extern "C" void kernel_launch(void* const* d_in, const int* in_sizes, int n_in,
                              void* d_out, int out_size) {
    const float* x1  = (const float*)d_in[0];  // xyz1_matrix [32,64,32,3]
    const float* x2  = (const float*)d_in[1];  // xyz2_matrix [32,64,32,3]
    float*       out = (float*)d_out;          // [32,64,64]
    chamfer_matrix_kernel<<<32 * 32, 256>>>(x1, x2, out);
}